// round 14
// baseline (speedup 1.0000x reference)
#include <cuda_runtime.h>
#include <string.h>

// HyperConv2dDepthWise: per-batch-weight 5x5 depthwise conv + bias + SiLU
// input:  (16, 128, 128, 128) f32   -> 2048 planes of 128x128
// weights:(16, 3328) f32            -> per (b,c): 25 taps at b*3328+c*25, bias at b*3328+3200+c
// output: (16, 128, 128, 128) f32
//
// Round-13: NO input smem, NO staging barrier. Scatter dataflow with each warp
// streaming its 12 input rows directly from global (3 overlapping LDG.128 per
// row). Row-OOB iterations (warp-uniform) skip load+contrib (zero padding);
// lane-0 A / lane-31 C stay zero via once-only init + lane-invariant predicated
// loads. Weights in a tiny smem bank (one early barrier). Horizontal f32x2
// packing, 5-deep accumulator ring, tanh packed SiLU, __stcs stores.

#define HW      128
#define BAND    32
#define WSTRIDE 3328           // 25*128 + 128
#define BOFF    3200           // 25*128

typedef unsigned long long ull;

__device__ __forceinline__ ull pair_of(float lo, float hi) {
    float2 t = make_float2(lo, hi);
    ull r;
    memcpy(&r, &t, 8);
    return r;
}
__device__ __forceinline__ void fma2(ull& d, ull a, ull b) {
    asm("fma.rn.f32x2 %0, %1, %2, %0;" : "+l"(d) : "l"(a), "l"(b));
}
__device__ __forceinline__ float2 unpk(ull v) {
    float2 f;
    memcpy(&f, &v, 8);
    return f;
}

// packed SiLU: silu(x) = h + h*tanh(h), h = 0.5*x   (tanh.approx HW op)
__device__ __forceinline__ ull silu2(ull acc, ull half2c) {
    ull h2;
    asm("mul.rn.f32x2 %0, %1, %2;" : "=l"(h2) : "l"(acc), "l"(half2c));
    float2 h = unpk(h2);
    float t0, t1;
    asm("tanh.approx.f32 %0, %1;" : "=f"(t0) : "f"(h.x));
    asm("tanh.approx.f32 %0, %1;" : "=f"(t1) : "f"(h.y));
    ull t2 = pair_of(t0, t1);
    ull r;
    asm("fma.rn.f32x2 %0, %1, %2, %1;" : "=l"(r) : "l"(h2), "l"(t2));
    return r;
}

// One packed row: covers logical cols x0-2 .. x0+5.
struct WRow {
    ull E0, E1, E2, E3, O0, O1, O2;
};

__device__ __forceinline__ void contrib5(ull& a0, ull& a1, const WRow& r,
                                         ull w0, ull w1, ull wc, ull w3, ull w4) {
    fma2(a0, w0, r.E0);  fma2(a1, w0, r.E1);
    fma2(a0, w1, r.O0);  fma2(a1, w1, r.O1);
    fma2(a0, wc, r.E1);  fma2(a1, wc, r.E2);
    fma2(a0, w3, r.O1);  fma2(a1, w3, r.O2);
    fma2(a0, w4, r.E2);  fma2(a1, w4, r.E3);
}

__global__ __launch_bounds__(128, 8)
void hconv_dw_kernel(const float* __restrict__ input,
                     const float* __restrict__ wts,
                     float* __restrict__ out)
{
    __shared__ alignas(16) ull wsm[5][8];   // 5 weight-row groups, padded

    const int bid   = blockIdx.x;
    const int band  = bid & 3;          // 4 bands of 32 rows per plane
    const int plane = bid >> 2;         // b*128 + c
    const int b     = plane >> 7;
    const int c     = plane & 127;

    const float* __restrict__ ip = input + (size_t)plane * (HW * HW);
    float* __restrict__ op       = out   + (size_t)plane * (HW * HW);

    const int tid  = threadIdx.x;
    const int lane = tid & 31;
    const int warp = tid >> 5;

    // ---- CTA-uniform packed weights -> tiny smem bank ----
    if (tid < 25) {
        const float w = __ldg(wts + b * WSTRIDE + c * 25 + tid);
        wsm[tid / 5][tid % 5] = pair_of(w, w);
    }
    const float bias = __ldg(wts + b * WSTRIDE + BOFF + c);
    const ull bias2  = pair_of(bias, bias);
    const ull half2c = pair_of(0.5f, 0.5f);
    __syncthreads();                    // weights visible; only barrier

    // ---- scatter compute: warp = full row width, 8 output rows per warp ----
    const int x0  = lane * 4;           // logical output col base
    const int gr0 = band * BAND + warp * 8;   // first output row (global, in-plane)

    const float* rp = ip + (gr0 - 2) * HW + x0;  // row pointer for rr = 0
    float* outp     = op + gr0 * HW + x0;

    const bool has_left  = (lane > 0);
    const bool has_right = (lane < 31);

    // ring of 5 in-flight accumulator pairs, indexed by output row % 5
    ull acc[5][2];

    // A (cols x0-4..x0-1) and C (cols x0+4..x0+7): zero once; lane 0 / lane 31
    // never overwrite them, giving correct zero padding at the column edges.
    float4 A = make_float4(0.f, 0.f, 0.f, 0.f);
    float4 C = make_float4(0.f, 0.f, 0.f, 0.f);
    float4 B;

#pragma unroll
    for (int rr = 0; rr < 12; rr++) {
        if (rr <= 7) {                  // birth of output rr
            acc[rr % 5][0] = bias2;
            acc[rr % 5][1] = bias2;
        }

        const int g = gr0 + rr - 2;     // input row (warp-uniform)
        if (g >= 0 && g < HW) {         // OOB rows contribute zero: skip all
            const float* p = rp + rr * HW;
            B = *(const float4*)(p);
            if (has_left)  A = *(const float4*)(p - 4);
            if (has_right) C = *(const float4*)(p + 4);

            WRow row;
            memcpy(&row.E0, &A.z, 8);
            memcpy(&row.E1, &B.x, 8);
            memcpy(&row.E2, &B.z, 8);
            memcpy(&row.E3, &C.x, 8);
            row.O0 = pair_of(A.w, B.x);
            row.O1 = pair_of(B.y, B.z);
            row.O2 = pair_of(B.w, C.x);

#pragma unroll
            for (int d = 0; d < 5; d++) {
                const int o = rr - d;
                if (o >= 0 && o <= 7) {
                    const ulonglong2 p01 = *(const ulonglong2*)&wsm[d][0];
                    const ulonglong2 p23 = *(const ulonglong2*)&wsm[d][2];
                    const ull w4 = wsm[d][4];
                    contrib5(acc[o % 5][0], acc[o % 5][1], row,
                             p01.x, p01.y, p23.x, p23.y, w4);
                }
            }
        }

        if (rr >= 4) {                  // output rr-4 complete
            const int o = rr - 4;
            const ull s0 = silu2(acc[o % 5][0], half2c);
            const ull s1 = silu2(acc[o % 5][1], half2c);
            float4 v;
            memcpy(&v.x, &s0, 8);
            memcpy(&v.z, &s1, 8);
            __stcs((float4*)(outp + o * HW), v);   // streaming store
        }
    }
}

extern "C" void kernel_launch(void* const* d_in, const int* in_sizes, int n_in,
                              void* d_out, int out_size)
{
    const float* input = (const float*)d_in[0];
    const float* wts   = (const float*)d_in[1];
    float* out         = (float*)d_out;

    // 2048 planes x 4 bands of 32 rows
    hconv_dw_kernel<<<8192, 128>>>(input, wts, out);
}

// round 17
// speedup vs baseline: 1.2213x; 1.2213x over previous
#include <cuda_runtime.h>
#include <string.h>

// HyperConv2dDepthWise: per-batch-weight 5x5 depthwise conv + bias + SiLU
// input:  (16, 128, 128, 128) f32   -> 2048 planes of 128x128
// weights:(16, 3328) f32            -> per (b,c): 25 taps at b*3328+c*25, bias at b*3328+3200+c
// output: (16, 128, 128, 128) f32
//
// Round-14: PER-WARP private cp.async staging (12 rows = 12 commit groups,
// one 16B chunk per lane per row -> MLP=12 front-batched), incremental
// wait_group(11-rr) + __syncwarp per consumed row -> no CTA staging barrier,
// compute overlaps the warp's own in-flight loads. Scatter dataflow,
// horizontal f32x2 packing, 5-deep acc ring, tanh packed SiLU, __stcs stores.

#define HW      128
#define BAND    32
#define WROWS   12             // rows staged per warp (8 outputs + 4 halo)
#define SPITCH  136            // floats; logical col L lives at smem col L+4
#define WSTRIDE 3328           // 25*128 + 128
#define BOFF    3200           // 25*128

typedef unsigned long long ull;

__device__ __forceinline__ ull pair_of(float lo, float hi) {
    float2 t = make_float2(lo, hi);
    ull r;
    memcpy(&r, &t, 8);
    return r;
}
__device__ __forceinline__ void fma2(ull& d, ull a, ull b) {
    asm("fma.rn.f32x2 %0, %1, %2, %0;" : "+l"(d) : "l"(a), "l"(b));
}
__device__ __forceinline__ float2 unpk(ull v) {
    float2 f;
    memcpy(&f, &v, 8);
    return f;
}

// packed SiLU: silu(x) = h + h*tanh(h), h = 0.5*x   (tanh.approx HW op)
__device__ __forceinline__ ull silu2(ull acc, ull half2c) {
    ull h2;
    asm("mul.rn.f32x2 %0, %1, %2;" : "=l"(h2) : "l"(acc), "l"(half2c));
    float2 h = unpk(h2);
    float t0, t1;
    asm("tanh.approx.f32 %0, %1;" : "=f"(t0) : "f"(h.x));
    asm("tanh.approx.f32 %0, %1;" : "=f"(t1) : "f"(h.y));
    ull t2 = pair_of(t0, t1);
    ull r;
    asm("fma.rn.f32x2 %0, %1, %2, %1;" : "=l"(r) : "l"(h2), "l"(t2));
    return r;
}

// One packed row: covers logical cols x0-2 .. x0+5.
struct WRow {
    ull E0, E1, E2, E3, O0, O1, O2;
};

__device__ __forceinline__ WRow load_row(const float* __restrict__ p) {
    float4 A = *(const float4*)(p);      // logical x0-4 .. x0-1
    float4 B = *(const float4*)(p + 4);  // logical x0   .. x0+3
    float4 C = *(const float4*)(p + 8);  // logical x0+4 .. x0+7
    WRow r;
    memcpy(&r.E0, &A.z, 8);
    memcpy(&r.E1, &B.x, 8);
    memcpy(&r.E2, &B.z, 8);
    memcpy(&r.E3, &C.x, 8);
    r.O0 = pair_of(A.w, B.x);
    r.O1 = pair_of(B.y, B.z);
    r.O2 = pair_of(B.w, C.x);
    return r;
}

__device__ __forceinline__ void contrib5(ull& a0, ull& a1, const WRow& r,
                                         ull w0, ull w1, ull wc, ull w3, ull w4) {
    fma2(a0, w0, r.E0);  fma2(a1, w0, r.E1);
    fma2(a0, w1, r.O0);  fma2(a1, w1, r.O1);
    fma2(a0, wc, r.E1);  fma2(a1, wc, r.E2);
    fma2(a0, w3, r.O1);  fma2(a1, w3, r.O2);
    fma2(a0, w4, r.E2);  fma2(a1, w4, r.E3);
}

__device__ __forceinline__ void cpa16(float* dst_s, const float* src_g, int sz) {
    const unsigned dst = (unsigned)__cvta_generic_to_shared(dst_s);
    asm volatile("cp.async.cg.shared.global [%0], [%1], 16, %2;\n"
                 :: "r"(dst), "l"(src_g), "r"(sz));
}

template <int N>
__device__ __forceinline__ void wait_groups() {
    asm volatile("cp.async.wait_group %0;\n" :: "n"(N) : "memory");
}
// wait until the oldest (12 - n_rem) groups are complete; n_rem = groups allowed outstanding
__device__ __forceinline__ void wait_upto(int n_rem) {
    switch (n_rem) {
        case 11: wait_groups<11>(); break;
        case 10: wait_groups<10>(); break;
        case 9:  wait_groups<9>();  break;
        case 8:  wait_groups<8>();  break;
        case 7:  wait_groups<7>();  break;
        case 6:  wait_groups<6>();  break;
        case 5:  wait_groups<5>();  break;
        case 4:  wait_groups<4>();  break;
        case 3:  wait_groups<3>();  break;
        case 2:  wait_groups<2>();  break;
        case 1:  wait_groups<1>();  break;
        default: wait_groups<0>();  break;
    }
}

__global__ __launch_bounds__(128, 8)
void hconv_dw_kernel(const float* __restrict__ input,
                     const float* __restrict__ wts,
                     float* __restrict__ out)
{
    __shared__ float sstage[4][WROWS * SPITCH];   // per-warp private staging
    __shared__ alignas(16) ull wsm[5][8];         // packed weight groups

    const int bid   = blockIdx.x;
    const int band  = bid & 3;          // 4 bands of 32 rows per plane
    const int plane = bid >> 2;         // b*128 + c
    const int b     = plane >> 7;
    const int c     = plane & 127;

    const float* __restrict__ ip = input + (size_t)plane * (HW * HW);
    float* __restrict__ op       = out   + (size_t)plane * (HW * HW);

    const int tid  = threadIdx.x;
    const int lane = tid & 31;
    const int warp = tid >> 5;

    const int gr0 = band * BAND + warp * 8;   // first output row of this warp
    float* wbuf = sstage[warp];

    // ---- issue this warp's 12 row loads: one 16B chunk per lane per row,
    //      one commit group per row (front-batched, MLP=12 per lane) ----
#pragma unroll
    for (int rr = 0; rr < WROWS; rr++) {
        const int g = gr0 + rr - 2;
        const bool ok = (g >= 0 && g < HW);
        cpa16(wbuf + rr * SPITCH + 4 + lane * 4,
              ip + (ok ? g : 0) * HW + lane * 4, ok ? 16 : 0);
        asm volatile("cp.async.commit_group;\n" ::: "memory");
    }

    // zero this warp's halo columns (quads 0 and 33, 12 rows -> 24 stores)
    if (lane < 24) {
        const int y = lane >> 1;
        const int q = (lane & 1) ? 33 : 0;
        *(float4*)(wbuf + y * SPITCH + q * 4) = make_float4(0.f, 0.f, 0.f, 0.f);
    }

    // ---- CTA-uniform packed weights -> tiny smem bank (overlaps cp.async) ----
    if (tid < 25) {
        const float w = __ldg(wts + b * WSTRIDE + c * 25 + tid);
        wsm[tid / 5][tid % 5] = pair_of(w, w);
    }
    const float bias = __ldg(wts + b * WSTRIDE + BOFF + c);
    const ull bias2  = pair_of(bias, bias);
    const ull half2c = pair_of(0.5f, 0.5f);
    __syncthreads();                    // weights visible (data loads still in flight)

    // ---- scatter compute, consuming rows as their groups complete ----
    const int x0 = lane * 4;            // logical output col base
    float* outp = op + gr0 * HW + x0;

    ull acc[5][2];                      // ring of 5 in-flight acc pairs

#pragma unroll
    for (int rr = 0; rr < WROWS; rr++) {
        wait_upto(WROWS - 1 - rr);      // oldest rr+1 groups complete
        __syncwarp();                   // all lanes' chunks of row rr visible

        const WRow row = load_row(wbuf + rr * SPITCH + x0);

        if (rr <= 7) {                  // birth of output rr
            acc[rr % 5][0] = bias2;
            acc[rr % 5][1] = bias2;
        }

#pragma unroll
        for (int d = 0; d < 5; d++) {
            const int o = rr - d;
            if (o >= 0 && o <= 7) {
                const ulonglong2 p01 = *(const ulonglong2*)&wsm[d][0];
                const ulonglong2 p23 = *(const ulonglong2*)&wsm[d][2];
                const ull w4 = wsm[d][4];
                contrib5(acc[o % 5][0], acc[o % 5][1], row,
                         p01.x, p01.y, p23.x, p23.y, w4);
            }
        }

        if (rr >= 4) {                  // output rr-4 complete
            const int o = rr - 4;
            const ull s0 = silu2(acc[o % 5][0], half2c);
            const ull s1 = silu2(acc[o % 5][1], half2c);
            float4 v;
            memcpy(&v.x, &s0, 8);
            memcpy(&v.z, &s1, 8);
            __stcs((float4*)(outp + o * HW), v);   // streaming store
        }
    }
}

extern "C" void kernel_launch(void* const* d_in, const int* in_sizes, int n_in,
                              void* d_out, int out_size)
{
    const float* input = (const float*)d_in[0];
    const float* wts   = (const float*)d_in[1];
    float* out         = (float*)d_out;

    // 2048 planes x 4 bands of 32 rows
    hconv_dw_kernel<<<8192, 128>>>(input, wts, out);
}